// round 7
// baseline (speedup 1.0000x reference)
#include <cuda_runtime.h>
#include <cuda_fp16.h>
#include <math.h>
#include <stdint.h>

#define BATCH 8192
#define U2    2048
#define GL    6144

#define BM 128
#define BN 256
#define BK 64
#define STAGES 4
#define THREADS 256

#define A_STAGE_BYTES (BM * BK * 2)            // 16384: 128 rows x 128B, SW128
#define BROWB 528                               // B smem row bytes (512 data + 16 pad)
#define B_STAGE_BYTES (BK * BROWB)              // 33792
#define STAGE_BYTES (A_STAGE_BYTES + B_STAGE_BYTES)   // 50176
#define SMEM_ALLOC (STAGES * STAGE_BYTES + 256)

#define NT_A 1024      // A tiles: 64 m-blocks x 16 n-tiles (m-major), K=4096
#define NTOT 1536      // + 512 B tiles: 64 m-blocks x 8 n-tiles, K=4096

// fp16 operand copies + intermediates (allocation-free scratch)
__device__ __half g_xH [(size_t)BATCH * U2];
__device__ __half g_hH [(size_t)BATCH * U2];
__device__ __half g_WinH[(size_t)U2 * GL];
__device__ __half g_WhH [(size_t)U2 * GL];
__device__ __half g_rhH[(size_t)BATCH * U2];   // fp16 r*h
__device__ float  g_U  [(size_t)BATCH * U2];   // update gate (fp32)

// scheduling state (reset each launch inside cvt kernel)
__device__ unsigned g_work;
__device__ unsigned g_done[64];

// ---------------- helpers ----------------
__device__ __forceinline__ uint32_t smem_u32(const void* p) {
    uint32_t a;
    asm("{ .reg .u64 t; cvta.to.shared.u64 t, %1; cvt.u32.u64 %0, t; }" : "=r"(a) : "l"(p));
    return a;
}
__device__ __forceinline__ void cp16(uint32_t dst, const void* src) {
    asm volatile("cp.async.cg.shared.global [%0], [%1], 16;" :: "r"(dst), "l"(src));
}
__device__ __forceinline__ void cp_commit() {
    asm volatile("cp.async.commit_group;" ::: "memory");
}
template<int N> __device__ __forceinline__ void cp_wait() {
    asm volatile("cp.async.wait_group %0;" :: "n"(N) : "memory");
}
__device__ __forceinline__ void ldsm_x4(uint32_t* r, uint32_t addr) {
    asm volatile("ldmatrix.sync.aligned.m8n8.x4.shared.b16 {%0,%1,%2,%3}, [%4];"
                 : "=r"(r[0]), "=r"(r[1]), "=r"(r[2]), "=r"(r[3]) : "r"(addr));
}
__device__ __forceinline__ void ldsm_x4_t(uint32_t* r, uint32_t addr) {
    asm volatile("ldmatrix.sync.aligned.m8n8.x4.trans.shared.b16 {%0,%1,%2,%3}, [%4];"
                 : "=r"(r[0]), "=r"(r[1]), "=r"(r[2]), "=r"(r[3]) : "r"(addr));
}
__device__ __forceinline__ void mma_f16(float* d, const uint32_t* a, const uint32_t* b) {
    asm volatile(
        "mma.sync.aligned.m16n8k16.row.col.f32.f16.f16.f32 "
        "{%0,%1,%2,%3}, {%4,%5,%6,%7}, {%8,%9}, {%0,%1,%2,%3};"
        : "+f"(d[0]), "+f"(d[1]), "+f"(d[2]), "+f"(d[3])
        : "r"(a[0]), "r"(a[1]), "r"(a[2]), "r"(a[3]), "r"(b[0]), "r"(b[1]));
}
__device__ __forceinline__ float sigmoidf_(float x) { return 1.0f / (1.0f + __expf(-x)); }

// ---------------- stage fill ----------------
__device__ __forceinline__ void fill_stage(int tid, uint32_t stA, uint32_t stB,
                                           int m0, int k0,
                                           const __half* aptr0, const __half* aptr1,
                                           const __half* bp0, const __half* bp1)
{
    // ---- A: row = tid>>1, 4 x 16B chunks (8 fp16 each) ----
    const int row = tid >> 1;
    const int c0a = (tid & 1) * 4;
#pragma unroll
    for (int j = 0; j < 4; j++) {
        const int ch = c0a + j;                  // 0..7
        const int kg = k0 + ch * 8;
        const __half* src = (kg < 2048)
            ? aptr0 + (size_t)(m0 + row) * U2 + kg
            : aptr1 + (size_t)(m0 + row) * U2 + (kg - 2048);
        cp16(stA + (uint32_t)(row << 7) + (uint32_t)(((ch ^ (row & 7)) << 4)), src);
    }
    // ---- B: k-row = tid>>2 (0..63), 8 x 16B chunks across 256 n ----
    const int kb = tid >> 2;
    const int kg = k0 + kb;
    const __half* brow = (kg < 2048)
        ? bp0 + (size_t)kg * GL
        : bp1 + (size_t)(kg - 2048) * GL;
    const uint32_t bbase = stB + (uint32_t)(kb * BROWB) + (uint32_t)((tid & 3) << 4);
#pragma unroll
    for (int q = 0; q < 8; q++)
        cp16(bbase + (uint32_t)(q << 6), brow + (tid & 3) * 8 + q * 32);
}

// ---------------- fused persistent GRU kernel ----------------
__global__ void __launch_bounds__(THREADS, 1)
gru_fused(const float* __restrict__ h_exact, const float* __restrict__ bias,
          float* __restrict__ out)
{
    extern __shared__ char smem_raw[];
    const uint32_t base = (smem_u32(smem_raw) + 127u) & ~127u;
    volatile int* sm_bcast = (volatile int*)(smem_raw + STAGES * STAGE_BYTES + 128);

    const int tid  = threadIdx.x;
    const int lane = tid & 31;
    const int wid  = tid >> 5;
    const int warp_m = wid & 1;
    const int warp_n = wid >> 1;

    // ldmatrix lane decomposition
    const int g = lane >> 3;
    const int r = lane & 7;
    const int a_mlocal = ((g & 1) << 3) + r;
    const int a_khalf  = g >> 1;
    const uint32_t a_rowoff = (uint32_t)((warp_m * 64 + a_mlocal) << 7);
    const int b_klocal = ((g & 1) << 3) + r;
    const int b_noct   = g >> 1;

    for (;;) {
        // ---- grab a tile ----
        if (tid == 0) *sm_bcast = (int)atomicAdd(&g_work, 1u);
        __syncthreads();
        const int t = *sm_bcast;
        if (t >= NTOT) break;

        // ---- decode (all tiles K=4096) ----
        int mblk, n0, region;
        const __half *aptr0, *aptr1, *bp0, *bp1;
        if (t < NT_A) {
            mblk = t >> 4;
            n0 = (t & 15) * 256;                 // gate column base (0..4095)
            region = n0 >> 11;                   // 0=r, 1=u
            aptr0 = g_xH;  aptr1 = g_hH;
            bp0 = g_WinH + n0;  bp1 = g_WhH + n0;
        } else {
            const int u = t - NT_A;
            mblk = u >> 3;
            n0 = (u & 7) * 256;                  // output column base (0..2047)
            region = 2;
            aptr0 = g_rhH;  aptr1 = g_xH;        // [rh | x]
            bp0 = g_WhH  + 4096 + n0;            // [Wh3 ; Win3]
            bp1 = g_WinH + 4096 + n0;
            // wait for this m-block's 16 A tiles (r and u gates)
            if (tid == 0) {
                while (atomicAdd(&g_done[mblk], 0u) < 16u) __nanosleep(128);
            }
            __syncthreads();
            __threadfence();
        }
        const int m0 = mblk * 128;
        const int NC = 4096 / BK;                // 64

        float d[4][8][4];
#pragma unroll
        for (int mf = 0; mf < 4; mf++)
#pragma unroll
            for (int nf = 0; nf < 8; nf++)
#pragma unroll
                for (int q = 0; q < 4; q++) d[mf][nf][q] = 0.0f;

        // ---- pipeline prologue ----
        fill_stage(tid, base, base + A_STAGE_BYTES, m0, 0, aptr0, aptr1, bp0, bp1);
        cp_commit();
        fill_stage(tid, base + STAGE_BYTES, base + STAGE_BYTES + A_STAGE_BYTES,
                   m0, BK, aptr0, aptr1, bp0, bp1);
        cp_commit();

        // ---- main K loop ----
        for (int c = 0; c < NC; c++) {
            if (c + 2 < NC) {
                const uint32_t sb = base + (uint32_t)((c + 2) % STAGES) * STAGE_BYTES;
                fill_stage(tid, sb, sb + A_STAGE_BYTES, m0, (c + 2) * BK,
                           aptr0, aptr1, bp0, bp1);
            }
            cp_commit();
            cp_wait<2>();
            __syncthreads();

            const uint32_t cs  = base + (uint32_t)(c % STAGES) * STAGE_BYTES;
            const uint32_t stB = cs + A_STAGE_BYTES;

#pragma unroll
            for (int ks = 0; ks < 4; ks++) {
                uint32_t a[4][4];
#pragma unroll
                for (int mf = 0; mf < 4; mf++) {
                    const uint32_t addr = cs + a_rowoff + (uint32_t)(mf << 11)
                                        + (uint32_t)((((ks << 1) + a_khalf) ^ r) << 4);
                    ldsm_x4(a[mf], addr);
                }
                uint32_t b[8][2];
#pragma unroll
                for (int pr = 0; pr < 4; pr++) {
                    uint32_t bb[4];
                    const uint32_t addr = stB
                        + (uint32_t)((ks * 16 + b_klocal) * BROWB)
                        + (uint32_t)((warp_n * 64 + pr * 16 + b_noct * 8) << 1);
                    ldsm_x4_t(bb, addr);
                    b[pr * 2 + 0][0] = bb[0]; b[pr * 2 + 0][1] = bb[1];
                    b[pr * 2 + 1][0] = bb[2]; b[pr * 2 + 1][1] = bb[3];
                }
#pragma unroll
                for (int mf = 0; mf < 4; mf++)
#pragma unroll
                    for (int nf = 0; nf < 8; nf++)
                        mma_f16(d[mf][nf], a[mf], b[nf]);
            }
        }
        cp_wait<0>();

        // ---- epilogue ----
#pragma unroll
        for (int mf = 0; mf < 4; mf++) {
#pragma unroll
            for (int nf = 0; nf < 8; nf++) {
                const int gc = n0 + warp_n * 64 + nf * 8 + (lane & 3) * 2;
#pragma unroll
                for (int half = 0; half < 2; half++) {
                    const int grow = m0 + warp_m * 64 + mf * 16 + (lane >> 2) + half * 8;
                    const float v0 = d[mf][nf][half * 2 + 0];
                    const float v1 = d[mf][nf][half * 2 + 1];
                    const size_t rb = (size_t)grow * U2;

                    if (region == 0) {
                        const int nl = gc;       // 0..2047
                        float2 bv = *(const float2*)(bias + gc);
                        float2 hv = *(const float2*)(h_exact + rb + nl);
                        __half2 o = __floats2half2_rn(sigmoidf_(v0 + bv.x) * hv.x,
                                                      sigmoidf_(v1 + bv.y) * hv.y);
                        *(__half2*)(g_rhH + rb + nl) = o;
                    } else if (region == 1) {
                        const int nl = gc & 2047;
                        float2 bv = *(const float2*)(bias + gc);
                        float2 o;
                        o.x = sigmoidf_(v0 + bv.x);
                        o.y = sigmoidf_(v1 + bv.y);
                        *(float2*)(g_U + rb + nl) = o;
                    } else {
                        float2 uu = *(const float2*)(g_U  + rb + gc);
                        float2 hv = *(const float2*)(h_exact + rb + gc);
                        float2 bv = *(const float2*)(bias + 4096 + gc);
                        float2 o;
                        const float c0 = tanhf(v0 + bv.x);
                        const float c1 = tanhf(v1 + bv.y);
                        o.x = uu.x * hv.x + (1.0f - uu.x) * c0;
                        o.y = uu.y * hv.y + (1.0f - uu.y) * c1;
                        *(float2*)(out + rb + gc) = o;
                    }
                }
            }
        }

        // ---- publish completion (A tiles) ----
        __threadfence();
        __syncthreads();                 // also protects sm_bcast reuse
        if (region < 2 && tid == 0) atomicAdd(&g_done[mblk], 1u);
    }
}

// ---------------- fused fp32 -> fp16 conversion + counter reset ----------------
__global__ void __launch_bounds__(256)
cvt_all_kernel(const float4* __restrict__ x, const float4* __restrict__ h,
               const float4* __restrict__ wi, const float4* __restrict__ wh)
{
    if (blockIdx.x == 0) {
        if (threadIdx.x < 64) g_done[threadIdx.x] = 0u;
        if (threadIdx.x == 64) g_work = 0u;
    }
    const int nx = BATCH * U2 / 4;
    const int nw = U2 * GL / 4;
    const int total = 2 * nx + 2 * nw;
    for (int i = blockIdx.x * blockDim.x + threadIdx.x; i < total;
         i += gridDim.x * blockDim.x) {
        const float4* src; __half2* dst; int j;
        if (i < nx)               { src = x;  dst = (__half2*)g_xH;   j = i; }
        else if (i < 2 * nx)      { src = h;  dst = (__half2*)g_hH;   j = i - nx; }
        else if (i < 2 * nx + nw) { src = wi; dst = (__half2*)g_WinH; j = i - 2 * nx; }
        else                      { src = wh; dst = (__half2*)g_WhH;  j = i - 2 * nx - nw; }
        float4 v = src[j];
        dst[2 * j + 0] = __floats2half2_rn(v.x, v.y);
        dst[2 * j + 1] = __floats2half2_rn(v.z, v.w);
    }
}

// ---------------- host ----------------
extern "C" void kernel_launch(void* const* d_in, const int* in_sizes, int n_in,
                              void* d_out, int out_size)
{
    const float* x    = (const float*)d_in[0];
    const float* h    = (const float*)d_in[1];
    const float* Win  = (const float*)d_in[2];
    const float* Wh   = (const float*)d_in[3];
    const float* bias = (const float*)d_in[4];
    float* out = (float*)d_out;

    static int nsm = 0;
    if (nsm == 0) {
        cudaDeviceGetAttribute(&nsm, cudaDevAttrMultiProcessorCount, 0);
        if (nsm <= 0) nsm = 148;
        cudaFuncSetAttribute(gru_fused, cudaFuncAttributeMaxDynamicSharedMemorySize,
                             SMEM_ALLOC);
    }

    cvt_all_kernel<<<2048, 256>>>((const float4*)x, (const float4*)h,
                                  (const float4*)Win, (const float4*)Wh);
    gru_fused<<<nsm, THREADS, SMEM_ALLOC>>>(h, bias, out);
}

// round 8
// speedup vs baseline: 1.3494x; 1.3494x over previous
#include <cuda_runtime.h>
#include <cuda_fp16.h>
#include <math.h>
#include <stdint.h>

#define BATCH 8192
#define U2    2048
#define GL    6144

#define BM 128
#define BN 256
#define BK 64
#define STAGES 4
#define THREADS 512

#define A_STAGE_BYTES (BM * BK * 2)            // 16384: 128 rows x 128B, SW128
#define BROWB 528                               // B smem row bytes (512 data + 16 pad)
#define B_STAGE_BYTES (BK * BROWB)              // 33792
#define STAGE_BYTES (A_STAGE_BYTES + B_STAGE_BYTES)   // 50176
#define SMEM_ALLOC (STAGES * STAGE_BYTES + 256)

#define NT_A 1536      // A tiles: 64 m-blocks x 24 n-tiles (m-major)
#define NTOT 2048      // + 512 B tiles: 64 m-blocks x 8 n-tiles

// fp16 operand copies + intermediates (allocation-free scratch)
__device__ __half g_xH [(size_t)BATCH * U2];
__device__ __half g_hH [(size_t)BATCH * U2];
__device__ __half g_WinH[(size_t)U2 * GL];
__device__ __half g_WhH [(size_t)U2 * GL];
__device__ __half g_rhH[(size_t)BATCH * U2];   // fp16 r*h
__device__ float  g_U  [(size_t)BATCH * U2];   // update gate (fp32)
__device__ float  g_XH [(size_t)BATCH * U2];   // x@Win[:,2u:] (fp32)

// scheduling state (reset each launch inside cvt kernel)
__device__ unsigned g_work;
__device__ unsigned g_done[64];

// ---------------- helpers ----------------
__device__ __forceinline__ uint32_t smem_u32(const void* p) {
    uint32_t a;
    asm("{ .reg .u64 t; cvta.to.shared.u64 t, %1; cvt.u32.u64 %0, t; }" : "=r"(a) : "l"(p));
    return a;
}
__device__ __forceinline__ void cp16(uint32_t dst, const void* src) {
    asm volatile("cp.async.cg.shared.global [%0], [%1], 16;" :: "r"(dst), "l"(src));
}
__device__ __forceinline__ void cp_commit() {
    asm volatile("cp.async.commit_group;" ::: "memory");
}
template<int N> __device__ __forceinline__ void cp_wait() {
    asm volatile("cp.async.wait_group %0;" :: "n"(N) : "memory");
}
__device__ __forceinline__ void ldsm_x4(uint32_t* r, uint32_t addr) {
    asm volatile("ldmatrix.sync.aligned.m8n8.x4.shared.b16 {%0,%1,%2,%3}, [%4];"
                 : "=r"(r[0]), "=r"(r[1]), "=r"(r[2]), "=r"(r[3]) : "r"(addr));
}
__device__ __forceinline__ void ldsm_x4_t(uint32_t* r, uint32_t addr) {
    asm volatile("ldmatrix.sync.aligned.m8n8.x4.trans.shared.b16 {%0,%1,%2,%3}, [%4];"
                 : "=r"(r[0]), "=r"(r[1]), "=r"(r[2]), "=r"(r[3]) : "r"(addr));
}
__device__ __forceinline__ void mma_f16(float* d, const uint32_t* a, const uint32_t* b) {
    asm volatile(
        "mma.sync.aligned.m16n8k16.row.col.f32.f16.f16.f32 "
        "{%0,%1,%2,%3}, {%4,%5,%6,%7}, {%8,%9}, {%0,%1,%2,%3};"
        : "+f"(d[0]), "+f"(d[1]), "+f"(d[2]), "+f"(d[3])
        : "r"(a[0]), "r"(a[1]), "r"(a[2]), "r"(a[3]), "r"(b[0]), "r"(b[1]));
}
__device__ __forceinline__ float sigmoidf_(float x) { return 1.0f / (1.0f + __expf(-x)); }

// ---------------- stage fill (512 threads) ----------------
__device__ __forceinline__ void fill_stage(int tid, uint32_t stA, uint32_t stB,
                                           int m0, int k0,
                                           const __half* aptr0, const __half* aptr1,
                                           const __half* bp0, const __half* bp1)
{
    // ---- A: row = tid>>2, 2 x 16B chunks each ----
    const int row = tid >> 2;
    const int c0a = (tid & 3) * 2;
#pragma unroll
    for (int j = 0; j < 2; j++) {
        const int ch = c0a + j;                  // 0..7
        const int kg = k0 + ch * 8;
        const __half* src = (kg < 2048)
            ? aptr0 + (size_t)(m0 + row) * U2 + kg
            : aptr1 + (size_t)(m0 + row) * U2 + (kg - 2048);
        cp16(stA + (uint32_t)(row << 7) + (uint32_t)(((ch ^ (row & 7)) << 4)), src);
    }
    // ---- B: k-row = tid>>3 (0..63), 4 x 16B chunks across 256 n ----
    const int kb = tid >> 3;
    const int kg = k0 + kb;
    const __half* brow = (kg < 2048)
        ? bp0 + (size_t)kg * GL
        : bp1 + (size_t)(kg - 2048) * GL;
    const uint32_t bbase = stB + (uint32_t)(kb * BROWB) + (uint32_t)((tid & 7) << 4);
#pragma unroll
    for (int q = 0; q < 4; q++)
        cp16(bbase + (uint32_t)(q << 7), brow + (tid & 7) * 8 + q * 64);
}

// ---------------- fused persistent GRU kernel ----------------
__global__ void __launch_bounds__(THREADS, 1)
gru_fused(const float* __restrict__ h_exact, const float* __restrict__ bias,
          float* __restrict__ out)
{
    extern __shared__ char smem_raw[];
    const uint32_t base = (smem_u32(smem_raw) + 127u) & ~127u;
    volatile int* sm_bcast = (volatile int*)(smem_raw + STAGES * STAGE_BYTES + 128);

    const int tid  = threadIdx.x;
    const int lane = tid & 31;
    const int wid  = tid >> 5;
    const int warp_m = wid & 3;          // 32-row quarters
    const int warp_n = wid >> 2;         // 64-col quarters

    // ldmatrix lane decomposition
    const int g = lane >> 3;
    const int r = lane & 7;
    const int a_mlocal = ((g & 1) << 3) + r;
    const int a_khalf  = g >> 1;
    const uint32_t a_rowoff = (uint32_t)((warp_m * 32 + a_mlocal) << 7);
    const int b_klocal = ((g & 1) << 3) + r;
    const int b_noct   = g >> 1;

    for (;;) {
        // ---- grab a tile ----
        if (tid == 0) *sm_bcast = (int)atomicAdd(&g_work, 1u);
        __syncthreads();
        const int t = *sm_bcast;
        if (t >= NTOT) break;

        // ---- decode ----
        int mblk, n0, K, region;
        const __half *aptr0, *aptr1, *bp0, *bp1;
        if (t < NT_A) {
            mblk = t / 24;
            const int nt = t % 24;
            n0 = nt * 256;                       // gate column base (0..6143)
            K  = (nt < 16) ? 4096 : 2048;
            region = n0 >> 11;                   // 0=r, 1=u, 2=xh
            aptr0 = g_xH;  aptr1 = g_hH;
            bp0 = g_WinH + n0;  bp1 = g_WhH + n0;
        } else {
            const int u = t - NT_A;
            mblk = u >> 3;
            n0 = (u & 7) * 256;                  // output column base (0..2047)
            K = 2048; region = 3;
            aptr0 = g_rhH;  aptr1 = g_rhH;
            bp0 = g_WhH + 4096 + n0;  bp1 = bp0;
            if (tid == 0) {
                while (atomicAdd(&g_done[mblk], 0u) < 24u) __nanosleep(128);
            }
            __syncthreads();
            __threadfence();
        }
        const int m0 = mblk * 128;
        const int NC = K / BK;

        float d[2][8][4];
#pragma unroll
        for (int mf = 0; mf < 2; mf++)
#pragma unroll
            for (int nf = 0; nf < 8; nf++)
#pragma unroll
                for (int q = 0; q < 4; q++) d[mf][nf][q] = 0.0f;

        // ---- pipeline prologue ----
        fill_stage(tid, base, base + A_STAGE_BYTES, m0, 0, aptr0, aptr1, bp0, bp1);
        cp_commit();
        fill_stage(tid, base + STAGE_BYTES, base + STAGE_BYTES + A_STAGE_BYTES,
                   m0, BK, aptr0, aptr1, bp0, bp1);
        cp_commit();

        // ---- main K loop ----
        for (int c = 0; c < NC; c++) {
            if (c + 2 < NC) {
                const uint32_t sb = base + (uint32_t)((c + 2) % STAGES) * STAGE_BYTES;
                fill_stage(tid, sb, sb + A_STAGE_BYTES, m0, (c + 2) * BK,
                           aptr0, aptr1, bp0, bp1);
            }
            cp_commit();
            cp_wait<2>();
            __syncthreads();

            const uint32_t cs  = base + (uint32_t)(c % STAGES) * STAGE_BYTES;
            const uint32_t stB = cs + A_STAGE_BYTES;

#pragma unroll
            for (int ks = 0; ks < 4; ks++) {
                uint32_t a[2][4];
#pragma unroll
                for (int mf = 0; mf < 2; mf++) {
                    const uint32_t addr = cs + a_rowoff + (uint32_t)(mf << 11)
                                        + (uint32_t)((((ks << 1) + a_khalf) ^ r) << 4);
                    ldsm_x4(a[mf], addr);
                }
                uint32_t b[8][2];
#pragma unroll
                for (int pr = 0; pr < 4; pr++) {
                    uint32_t bb[4];
                    const uint32_t addr = stB
                        + (uint32_t)((ks * 16 + b_klocal) * BROWB)
                        + (uint32_t)((warp_n * 64 + pr * 16 + b_noct * 8) << 1);
                    ldsm_x4_t(bb, addr);
                    b[pr * 2 + 0][0] = bb[0]; b[pr * 2 + 0][1] = bb[1];
                    b[pr * 2 + 1][0] = bb[2]; b[pr * 2 + 1][1] = bb[3];
                }
#pragma unroll
                for (int mf = 0; mf < 2; mf++)
#pragma unroll
                    for (int nf = 0; nf < 8; nf++)
                        mma_f16(d[mf][nf], a[mf], b[nf]);
            }
        }
        cp_wait<0>();

        // ---- epilogue ----
#pragma unroll
        for (int mf = 0; mf < 2; mf++) {
#pragma unroll
            for (int nf = 0; nf < 8; nf++) {
                const int gc = n0 + warp_n * 64 + nf * 8 + (lane & 3) * 2;
#pragma unroll
                for (int half = 0; half < 2; half++) {
                    const int grow = m0 + warp_m * 32 + mf * 16 + (lane >> 2) + half * 8;
                    const float v0 = d[mf][nf][half * 2 + 0];
                    const float v1 = d[mf][nf][half * 2 + 1];
                    const size_t rb = (size_t)grow * U2;

                    if (region == 0) {
                        const int nl = gc;
                        float2 bv = *(const float2*)(bias + gc);
                        float2 hv = *(const float2*)(h_exact + rb + nl);
                        __half2 o = __floats2half2_rn(sigmoidf_(v0 + bv.x) * hv.x,
                                                      sigmoidf_(v1 + bv.y) * hv.y);
                        *(__half2*)(g_rhH + rb + nl) = o;
                    } else if (region == 1) {
                        const int nl = gc & 2047;
                        float2 bv = *(const float2*)(bias + gc);
                        float2 o;
                        o.x = sigmoidf_(v0 + bv.x);
                        o.y = sigmoidf_(v1 + bv.y);
                        *(float2*)(g_U + rb + nl) = o;
                    } else if (region == 2) {
                        const int nl = gc & 2047;
                        float2 o; o.x = v0; o.y = v1;
                        *(float2*)(g_XH + rb + nl) = o;
                    } else {
                        float2 xh = *(const float2*)(g_XH + rb + gc);
                        float2 uu = *(const float2*)(g_U  + rb + gc);
                        float2 hv = *(const float2*)(h_exact + rb + gc);
                        float2 bv = *(const float2*)(bias + 4096 + gc);
                        float2 o;
                        const float c0 = tanhf(v0 + xh.x + bv.x);
                        const float c1 = tanhf(v1 + xh.y + bv.y);
                        o.x = uu.x * hv.x + (1.0f - uu.x) * c0;
                        o.y = uu.y * hv.y + (1.0f - uu.y) * c1;
                        *(float2*)(out + rb + gc) = o;
                    }
                }
            }
        }

        // ---- publish completion (A tiles) ----
        __threadfence();
        __syncthreads();                 // also protects sm_bcast reuse
        if (region < 3 && tid == 0) atomicAdd(&g_done[mblk], 1u);
    }
}

// ---------------- fused fp32 -> fp16 conversion + counter reset ----------------
__global__ void __launch_bounds__(256)
cvt_all_kernel(const float4* __restrict__ x, const float4* __restrict__ h,
               const float4* __restrict__ wi, const float4* __restrict__ wh)
{
    if (blockIdx.x == 0) {
        if (threadIdx.x < 64) g_done[threadIdx.x] = 0u;
        if (threadIdx.x == 64) g_work = 0u;
    }
    const int nx = BATCH * U2 / 4;
    const int nw = U2 * GL / 4;
    const int total = 2 * nx + 2 * nw;
    for (int i = blockIdx.x * blockDim.x + threadIdx.x; i < total;
         i += gridDim.x * blockDim.x) {
        const float4* src; __half2* dst; int j;
        if (i < nx)               { src = x;  dst = (__half2*)g_xH;   j = i; }
        else if (i < 2 * nx)      { src = h;  dst = (__half2*)g_hH;   j = i - nx; }
        else if (i < 2 * nx + nw) { src = wi; dst = (__half2*)g_WinH; j = i - 2 * nx; }
        else                      { src = wh; dst = (__half2*)g_WhH;  j = i - 2 * nx - nw; }
        float4 v = src[j];
        dst[2 * j + 0] = __floats2half2_rn(v.x, v.y);
        dst[2 * j + 1] = __floats2half2_rn(v.z, v.w);
    }
}

// ---------------- host ----------------
extern "C" void kernel_launch(void* const* d_in, const int* in_sizes, int n_in,
                              void* d_out, int out_size)
{
    const float* x    = (const float*)d_in[0];
    const float* h    = (const float*)d_in[1];
    const float* Win  = (const float*)d_in[2];
    const float* Wh   = (const float*)d_in[3];
    const float* bias = (const float*)d_in[4];
    float* out = (float*)d_out;

    static int nsm = 0;
    if (nsm == 0) {
        cudaDeviceGetAttribute(&nsm, cudaDevAttrMultiProcessorCount, 0);
        if (nsm <= 0) nsm = 148;
        cudaFuncSetAttribute(gru_fused, cudaFuncAttributeMaxDynamicSharedMemorySize,
                             SMEM_ALLOC);
    }

    cvt_all_kernel<<<2048, 256>>>((const float4*)x, (const float4*)h,
                                  (const float4*)Win, (const float4*)Wh);
    gru_fused<<<nsm, THREADS, SMEM_ALLOC>>>(h, bias, out);
}